// round 1
// baseline (speedup 1.0000x reference)
#include <cuda_runtime.h>
#include <math.h>

#define NNODE 20
#define NEDGE 380
#define HID   64
#define NL    3
#define NTILE 6      // ceil(380/64)
#define SA    68     // stride for A1 / M tiles (float4-friendly, conflict relief)
#define SH    65     // stride for h-like [20][64] arrays (scalar access)
#define BLK   256
#define NB    1024

__device__ __forceinline__ float silu_f(float v){ return v / (1.f + __expf(-v)); }
__device__ __forceinline__ float sigm_f(float v){ return 1.f / (1.f + __expf(-v)); }

// shared memory layout (floats):
//  x0[20] x1[20] aggx[20] aggy[20]                          80
//  hS[20*65] hA[20*65] hB[20*65] mag[20*65]               5200
//  W2s[4096] C1s[4096]                                    8192
//  A1[64*68] Mm[64*68]                                    8704
//  w1c b1v b2v avv cb1v c2v  (6*64)                        384
//  sigv cdx cdy (3*64)                                     192
#define SMEM_FLOATS (80 + 4*NNODE*SH + 2*HID*HID + 2*64*SA + 6*64 + 3*64)

__global__ void __launch_bounds__(BLK)
egnn_critic_kernel(
    const float* __restrict__ obs,   const float* __restrict__ rnn,
    const float* __restrict__ emb_w, const float* __restrict__ emb_b,
    const float* __restrict__ ew1,   const float* __restrict__ eb1,
    const float* __restrict__ ew2,   const float* __restrict__ eb2,
    const float* __restrict__ attw,  const float* __restrict__ attb,
    const float* __restrict__ nw1,   const float* __restrict__ nb1,
    const float* __restrict__ nw2,   const float* __restrict__ nb2,
    const float* __restrict__ cw1,   const float* __restrict__ cb1,
    const float* __restrict__ cw2,
    const float* __restrict__ fc1w,  const float* __restrict__ fc1b,
    const float* __restrict__ fc2w,  const float* __restrict__ fc2b,
    float* __restrict__ out, int copy_rnn)
{
    extern __shared__ float sm[];
    float* x0   = sm;
    float* x1   = x0 + NNODE;
    float* aggx = x1 + NNODE;
    float* aggy = aggx + NNODE;
    float* hS   = aggy + NNODE;          // [20][SH]
    float* hA   = hS + NNODE*SH;
    float* hB   = hA + NNODE*SH;
    float* mag  = hB + NNODE*SH;
    float* W2s  = mag + NNODE*SH;        // [64][64] row-major [k][o]
    float* C1s  = W2s + HID*HID;
    float* A1   = C1s + HID*HID;         // [64][SA]
    float* Mm   = A1 + 64*SA;            // [64][SA]
    float* w1c  = Mm + 64*SA;
    float* b1v  = w1c + 64;
    float* b2v  = b1v + 64;
    float* avv  = b2v + 64;
    float* cb1v = avv + 64;
    float* c2v  = cb1v + 64;
    float* sigv = c2v + 64;
    float* cdx  = sigv + 64;
    float* cdy  = cdx + 64;

    const int g = blockIdx.x;
    const int t = threadIdx.x;
    const float* ob = obs + g * NNODE * 10;   // EQU+INV = 10 per node

    // ---- init x, h ----
    if (t < NNODE){ x0[t] = ob[t*10 + 0]; x1[t] = ob[t*10 + 1]; }
    {
        int d = t & 63, ng = t >> 6;
        #pragma unroll
        for (int q = 0; q < 5; ++q){
            int n = ng + 4*q;
            float acc = emb_b[d];
            #pragma unroll
            for (int k = 0; k < 8; ++k) acc += ob[n*10 + 2 + k] * __ldg(emb_w + k*64 + d);
            hS[n*SH + d] = acc;
        }
    }
    __syncthreads();

    for (int l = 0; l < NL; ++l){
        // ---- per-layer weights into SMEM, zero accumulators ----
        {
            const float* ew2l = ew2 + l*4096;
            const float* cw1l = cw1 + l*4096;
            for (int i = t; i < 4096; i += BLK){ W2s[i] = ew2l[i]; C1s[i] = cw1l[i]; }
            if (t < 64){
                w1c[t]  = ew1[l*129*64 + 128*64 + t];
                b1v[t]  = eb1[l*64 + t];
                b2v[t]  = eb2[l*64 + t];
                avv[t]  = attw[l*64 + t];
                cb1v[t] = cb1[l*64 + t];
                c2v[t]  = cw2[l*64 + t];
            }
            if (t < NNODE){ aggx[t] = 0.f; aggy[t] = 0.f; }
            for (int i = t; i < NNODE*SH; i += BLK) mag[i] = 0.f;
        }
        __syncthreads();

        // ---- hA = h @ W1[0:64], hB = h @ W1[64:128]  (per node) ----
        {
            int d = t & 63, ng = t >> 6;
            float aA[5], aB[5];
            #pragma unroll
            for (int q = 0; q < 5; ++q){ aA[q] = 0.f; aB[q] = 0.f; }
            const float* w1l = ew1 + l*129*64;
            for (int k = 0; k < 64; ++k){
                float wa = __ldg(w1l + k*64 + d);
                float wb = __ldg(w1l + (64 + k)*64 + d);
                #pragma unroll
                for (int q = 0; q < 5; ++q){
                    float hv = hS[(ng + 4*q)*SH + k];
                    aA[q] = fmaf(hv, wa, aA[q]);
                    aB[q] = fmaf(hv, wb, aB[q]);
                }
            }
            #pragma unroll
            for (int q = 0; q < 5; ++q){
                hA[(ng + 4*q)*SH + d] = aA[q];
                hB[(ng + 4*q)*SH + d] = aB[q];
            }
        }
        __syncthreads();

        // ---- edge tiles ----
        for (int tile = 0; tile < NTILE; ++tile){
            const int e0 = tile * 64;

            // build t1 = silu(hA[r] + hB[c] + radial*w1c + b1)
            {
                int le = t & 63, kg = t >> 6;
                int e = e0 + le;
                bool v = (e < NEDGE);
                int r = 0, c = 0; float radial = 0.f;
                if (v){
                    r = e / 19; int jj = e - r*19; c = jj + (jj >= r);
                    float dx = x0[r] - x0[c], dy = x1[r] - x1[c];
                    radial = dx*dx + dy*dy;
                    if (kg == 0){
                        float inv = 1.f / (sqrtf(radial) + 1e-8f);
                        cdx[le] = dx * inv; cdy[le] = dy * inv;
                    }
                }
                #pragma unroll 4
                for (int kk = 0; kk < 16; ++kk){
                    int k = kg*16 + kk;
                    float o = 0.f;
                    if (v){
                        float pre = hA[r*SH + k] + hB[c*SH + k] + radial*w1c[k] + b1v[k];
                        o = silu_f(pre);
                    }
                    A1[le*SA + k] = o;
                }
            }
            __syncthreads();

            // GEMM1: t2 = silu(A1 @ W2 + b2); store to Mm; att partial + sigmoid
            {
                int tx = t & 15, ty = t >> 4;
                float acc[4][4];
                #pragma unroll
                for (int i = 0; i < 4; ++i)
                    #pragma unroll
                    for (int j = 0; j < 4; ++j) acc[i][j] = 0.f;
                #pragma unroll 8
                for (int k = 0; k < 64; ++k){
                    float4 b = *(const float4*)(W2s + k*64 + tx*4);
                    float a0 = A1[(4*ty+0)*SA + k];
                    float a1 = A1[(4*ty+1)*SA + k];
                    float a2 = A1[(4*ty+2)*SA + k];
                    float a3 = A1[(4*ty+3)*SA + k];
                    acc[0][0]=fmaf(a0,b.x,acc[0][0]); acc[0][1]=fmaf(a0,b.y,acc[0][1]);
                    acc[0][2]=fmaf(a0,b.z,acc[0][2]); acc[0][3]=fmaf(a0,b.w,acc[0][3]);
                    acc[1][0]=fmaf(a1,b.x,acc[1][0]); acc[1][1]=fmaf(a1,b.y,acc[1][1]);
                    acc[1][2]=fmaf(a1,b.z,acc[1][2]); acc[1][3]=fmaf(a1,b.w,acc[1][3]);
                    acc[2][0]=fmaf(a2,b.x,acc[2][0]); acc[2][1]=fmaf(a2,b.y,acc[2][1]);
                    acc[2][2]=fmaf(a2,b.z,acc[2][2]); acc[2][3]=fmaf(a2,b.w,acc[2][3]);
                    acc[3][0]=fmaf(a3,b.x,acc[3][0]); acc[3][1]=fmaf(a3,b.y,acc[3][1]);
                    acc[3][2]=fmaf(a3,b.z,acc[3][2]); acc[3][3]=fmaf(a3,b.w,acc[3][3]);
                }
                float attp[4];
                #pragma unroll
                for (int i = 0; i < 4; ++i){
                    float4 mv; float s = 0.f;
                    #pragma unroll
                    for (int j = 0; j < 4; ++j){
                        float z = silu_f(acc[i][j] + b2v[4*tx + j]);
                        ((float*)&mv)[j] = z;
                        s = fmaf(z, avv[4*tx + j], s);
                    }
                    *(float4*)(Mm + (4*ty + i)*SA + 4*tx) = mv;
                    attp[i] = s;
                }
                #pragma unroll
                for (int m = 8; m >= 1; m >>= 1){
                    #pragma unroll
                    for (int i = 0; i < 4; ++i)
                        attp[i] += __shfl_xor_sync(0xffffffffu, attp[i], m, 16);
                }
                if (tx == 0){
                    float ab = __ldg(attb + l);
                    #pragma unroll
                    for (int i = 0; i < 4; ++i) sigv[4*ty + i] = sigm_f(attp[i] + ab);
                }
            }
            __syncthreads();

            // gate m = t2 * sigmoid(att), accumulate m_agg (segment sum over rows)
            {
                int o = t & 63, lg = t >> 6;
                float acc = 0.f; int curr = -1;
                for (int le = lg*16; le < lg*16 + 16; ++le){
                    int e = e0 + le;
                    if (e < NEDGE){
                        float mv = Mm[le*SA + o] * sigv[le];
                        Mm[le*SA + o] = mv;
                        int r = e / 19;
                        if (r != curr){
                            if (curr >= 0) atomicAdd(mag + curr*SH + o, acc);
                            curr = r; acc = 0.f;
                        }
                        acc += mv;
                    }
                }
                if (curr >= 0) atomicAdd(mag + curr*SH + o, acc);
            }
            __syncthreads();

            // GEMM2: t3 = silu(M @ cw1 + cb1); w = tanh(t3 @ cw2); scatter coords
            {
                int tx = t & 15, ty = t >> 4;
                float acc[4][4];
                #pragma unroll
                for (int i = 0; i < 4; ++i)
                    #pragma unroll
                    for (int j = 0; j < 4; ++j) acc[i][j] = 0.f;
                #pragma unroll 8
                for (int k = 0; k < 64; ++k){
                    float4 b = *(const float4*)(C1s + k*64 + tx*4);
                    float a0 = Mm[(4*ty+0)*SA + k];
                    float a1 = Mm[(4*ty+1)*SA + k];
                    float a2 = Mm[(4*ty+2)*SA + k];
                    float a3 = Mm[(4*ty+3)*SA + k];
                    acc[0][0]=fmaf(a0,b.x,acc[0][0]); acc[0][1]=fmaf(a0,b.y,acc[0][1]);
                    acc[0][2]=fmaf(a0,b.z,acc[0][2]); acc[0][3]=fmaf(a0,b.w,acc[0][3]);
                    acc[1][0]=fmaf(a1,b.x,acc[1][0]); acc[1][1]=fmaf(a1,b.y,acc[1][1]);
                    acc[1][2]=fmaf(a1,b.z,acc[1][2]); acc[1][3]=fmaf(a1,b.w,acc[1][3]);
                    acc[2][0]=fmaf(a2,b.x,acc[2][0]); acc[2][1]=fmaf(a2,b.y,acc[2][1]);
                    acc[2][2]=fmaf(a2,b.z,acc[2][2]); acc[2][3]=fmaf(a2,b.w,acc[2][3]);
                    acc[3][0]=fmaf(a3,b.x,acc[3][0]); acc[3][1]=fmaf(a3,b.y,acc[3][1]);
                    acc[3][2]=fmaf(a3,b.z,acc[3][2]); acc[3][3]=fmaf(a3,b.w,acc[3][3]);
                }
                float wp[4];
                #pragma unroll
                for (int i = 0; i < 4; ++i){
                    float s = 0.f;
                    #pragma unroll
                    for (int j = 0; j < 4; ++j){
                        float z = silu_f(acc[i][j] + cb1v[4*tx + j]);
                        s = fmaf(z, c2v[4*tx + j], s);
                    }
                    wp[i] = s;
                }
                #pragma unroll
                for (int m = 8; m >= 1; m >>= 1){
                    #pragma unroll
                    for (int i = 0; i < 4; ++i)
                        wp[i] += __shfl_xor_sync(0xffffffffu, wp[i], m, 16);
                }
                if (tx == 0){
                    #pragma unroll
                    for (int i = 0; i < 4; ++i){
                        int le = 4*ty + i, e = e0 + le;
                        if (e < NEDGE){
                            float w = tanhf(wp[i]);
                            int r = e / 19;
                            atomicAdd(aggx + r, cdx[le] * w);
                            atomicAdd(aggy + r, cdy[le] * w);
                        }
                    }
                }
            }
            __syncthreads();
        } // tiles

        // ---- x update (cnt == 19 exactly for full graph) ----
        if (t < NNODE){
            x0[t] += aggx[t] * (1.f/19.f);
            x1[t] += aggy[t] * (1.f/19.f);
        }

        // ---- node MLP: h += silu([h,m_agg]@nw1+nb1) @ nw2 + nb2 ----
        float* z1 = A1;  // reuse
        {
            int o = t & 63, ng = t >> 6;
            float acc[5];
            float bb = __ldg(nb1 + l*64 + o);
            #pragma unroll
            for (int q = 0; q < 5; ++q) acc[q] = bb;
            const float* w1 = nw1 + l*128*64;
            for (int k = 0; k < 64; ++k){
                float w = __ldg(w1 + k*64 + o);
                #pragma unroll
                for (int q = 0; q < 5; ++q) acc[q] = fmaf(hS[(ng+4*q)*SH + k], w, acc[q]);
            }
            for (int k = 0; k < 64; ++k){
                float w = __ldg(w1 + (64 + k)*64 + o);
                #pragma unroll
                for (int q = 0; q < 5; ++q) acc[q] = fmaf(mag[(ng+4*q)*SH + k], w, acc[q]);
            }
            #pragma unroll
            for (int q = 0; q < 5; ++q) z1[(ng+4*q)*SA + o] = silu_f(acc[q]);
        }
        __syncthreads();
        {
            int o = t & 63, ng = t >> 6;
            float acc[5];
            float bb = __ldg(nb2 + l*64 + o);
            #pragma unroll
            for (int q = 0; q < 5; ++q) acc[q] = bb;
            const float* w2 = nw2 + l*4096;
            for (int k = 0; k < 64; ++k){
                float w = __ldg(w2 + k*64 + o);
                #pragma unroll
                for (int q = 0; q < 5; ++q) acc[q] = fmaf(z1[(ng+4*q)*SA + k], w, acc[q]);
            }
            #pragma unroll
            for (int q = 0; q < 5; ++q) hS[(ng+4*q)*SH + o] += acc[q];
        }
        __syncthreads();
    } // layers

    // ---- value head ----
    float* z1 = A1;
    {
        int o = t & 63, ng = t >> 6;
        float acc[5];
        #pragma unroll
        for (int q = 0; q < 5; ++q){
            int n = ng + 4*q;
            float xsq = x0[n]*x0[n] + x1[n]*x1[n];
            acc[q] = fmaf(xsq, __ldg(fc1w + o), fc1b[o]);
        }
        for (int k = 0; k < 64; ++k){
            float w = __ldg(fc1w + (1 + k)*64 + o);
            #pragma unroll
            for (int q = 0; q < 5; ++q) acc[q] = fmaf(hS[(ng+4*q)*SH + k], w, acc[q]);
        }
        #pragma unroll
        for (int q = 0; q < 5; ++q) z1[(ng+4*q)*SA + o] = tanhf(acc[q]);
    }
    __syncthreads();
    if (t < 32){
        float v = 0.f;
        if (t < NNODE){
            v = __ldg(fc2b);
            for (int o = 0; o < 64; ++o) v = fmaf(z1[t*SA + o], __ldg(fc2w + o), v);
        }
        #pragma unroll
        for (int m = 16; m >= 1; m >>= 1) v += __shfl_xor_sync(0xffffffffu, v, m);
        if (t == 0) out[g] = v * (1.f / NNODE);
    }
    // rnn_states passthrough
    if (copy_rnn && t < 64) out[NB + g*64 + t] = rnn[g*64 + t];
}

extern "C" void kernel_launch(void* const* d_in, const int* in_sizes, int n_in,
                              void* d_out, int out_size)
{
    const float* obs   = (const float*)d_in[0];
    const float* rnn   = (const float*)d_in[1];
    // d_in[2] = masks (unused)
    const float* emb_w = (const float*)d_in[3];
    const float* emb_b = (const float*)d_in[4];
    const float* ew1   = (const float*)d_in[5];
    const float* eb1   = (const float*)d_in[6];
    const float* ew2   = (const float*)d_in[7];
    const float* eb2   = (const float*)d_in[8];
    const float* attw  = (const float*)d_in[9];
    const float* attb  = (const float*)d_in[10];
    const float* nw1   = (const float*)d_in[11];
    const float* nb1   = (const float*)d_in[12];
    const float* nw2   = (const float*)d_in[13];
    const float* nb2   = (const float*)d_in[14];
    const float* cw1   = (const float*)d_in[15];
    const float* cb1   = (const float*)d_in[16];
    const float* cw2   = (const float*)d_in[17];
    const float* fc1w  = (const float*)d_in[18];
    const float* fc1b  = (const float*)d_in[19];
    const float* fc2w  = (const float*)d_in[20];
    const float* fc2b  = (const float*)d_in[21];
    // d_in[22], d_in[23] = edge_row/edge_col (recomputed analytically)

    const size_t smem_bytes = (size_t)SMEM_FLOATS * sizeof(float);
    cudaFuncSetAttribute(egnn_critic_kernel,
                         cudaFuncAttributeMaxDynamicSharedMemorySize,
                         (int)smem_bytes);

    int copy_rnn = (out_size >= NB + NB*HID) ? 1 : 0;

    egnn_critic_kernel<<<NB, BLK, smem_bytes>>>(
        obs, rnn, emb_w, emb_b, ew1, eb1, ew2, eb2, attw, attb,
        nw1, nb1, nw2, nb2, cw1, cb1, cw2, fc1w, fc1b, fc2w, fc2b,
        (float*)d_out, copy_rnn);
}

// round 2
// speedup vs baseline: 1.2270x; 1.2270x over previous
#include <cuda_runtime.h>
#include <math.h>

#define NNODE 20
#define NEDGE 380
#define HID   64
#define NL    3
#define NTILE 6      // ceil(380/64)
#define SH    65     // stride for h-like [20][*] arrays (bank spread for c-indexed reads)
#define SMM   68     // Mm edge-major stride (float4 aligned, conflict-free row writes)
#define BLK   256
#define NB    1024

__device__ __forceinline__ float silu_f(float v){ return v / (1.f + __expf(-v)); }
__device__ __forceinline__ float sigm_f(float v){ return 1.f / (1.f + __expf(-v)); }

// smem floats:
//  x0,x1,aggx,aggy                  80
//  hS,hA,hB,mag   4*20*65         5200
//  A1 (k-major)   64*64           4096
//  Mm (edge-major)64*68           4352
//  w1c,b1v,b2v,avv,cb1v,c2v        384
//  cdx,cdy                         128
//  abv                               4
#define SMEM_FLOATS (80 + 4*NNODE*SH + HID*HID + 64*SMM + 6*64 + 2*64 + 4)

__global__ void __launch_bounds__(BLK, 4)
egnn_critic_kernel(
    const float* __restrict__ obs,   const float* __restrict__ rnn,
    const float* __restrict__ emb_w, const float* __restrict__ emb_b,
    const float* __restrict__ ew1,   const float* __restrict__ eb1,
    const float* __restrict__ ew2,   const float* __restrict__ eb2,
    const float* __restrict__ attw,  const float* __restrict__ attb,
    const float* __restrict__ nw1,   const float* __restrict__ nb1,
    const float* __restrict__ nw2,   const float* __restrict__ nb2,
    const float* __restrict__ cw1,   const float* __restrict__ cb1,
    const float* __restrict__ cw2,
    const float* __restrict__ fc1w,  const float* __restrict__ fc1b,
    const float* __restrict__ fc2w,  const float* __restrict__ fc2b,
    float* __restrict__ out, int copy_rnn)
{
    extern __shared__ float sm[];
    float* x0   = sm;
    float* x1   = x0 + NNODE;
    float* aggx = x1 + NNODE;
    float* aggy = aggx + NNODE;
    float* hS   = aggy + NNODE;          // [20][SH]
    float* hA   = hS + NNODE*SH;
    float* hB   = hA + NNODE*SH;
    float* mag  = hB + NNODE*SH;
    float* A1   = mag + NNODE*SH;        // k-major [64][64]
    float* Mm   = A1 + HID*HID;          // edge-major [64][SMM]
    float* w1c  = Mm + 64*SMM;
    float* b1v  = w1c + 64;
    float* b2v  = b1v + 64;
    float* avv  = b2v + 64;
    float* cb1v = avv + 64;
    float* c2v  = cb1v + 64;
    float* cdx  = c2v + 64;
    float* cdy  = cdx + 64;
    float* abv  = cdy + 64;

    const int g = blockIdx.x;
    const int t = threadIdx.x;
    const float* ob = obs + g * NNODE * 10;   // EQU+INV = 10 per node

    // ---- init x, h ----
    if (t < NNODE){ x0[t] = ob[t*10 + 0]; x1[t] = ob[t*10 + 1]; }
    {
        int d = t & 63, ng = t >> 6;
        #pragma unroll
        for (int q = 0; q < 5; ++q){
            int n = ng + 4*q;
            float acc = emb_b[d];
            #pragma unroll
            for (int k = 0; k < 8; ++k) acc += ob[n*10 + 2 + k] * __ldg(emb_w + k*64 + d);
            hS[n*SH + d] = acc;
        }
    }
    __syncthreads();

    for (int l = 0; l < NL; ++l){
        // ---- stage per-layer vectors, zero accumulators ----
        if (t < 64){
            w1c[t]  = ew1[l*129*64 + 128*64 + t];
            b1v[t]  = eb1[l*64 + t];
            b2v[t]  = eb2[l*64 + t];
            avv[t]  = attw[l*64 + t];
            cb1v[t] = cb1[l*64 + t];
            c2v[t]  = cw2[l*64 + t];
        }
        if (t == 64) abv[0] = attb[l];
        if (t < NNODE){ aggx[t] = 0.f; aggy[t] = 0.f; }
        for (int i = t; i < NNODE*SH; i += BLK) mag[i] = 0.f;
        __syncthreads();

        // ---- hA = h @ W1[0:64], hB = h @ W1[64:128]  (per node) ----
        {
            int d = t & 63, ng = t >> 6;
            float aA[5], aB[5];
            #pragma unroll
            for (int q = 0; q < 5; ++q){ aA[q] = 0.f; aB[q] = 0.f; }
            const float* w1l = ew1 + l*129*64;
            for (int k = 0; k < 64; ++k){
                float wa = __ldg(w1l + k*64 + d);
                float wb = __ldg(w1l + (64 + k)*64 + d);
                #pragma unroll
                for (int q = 0; q < 5; ++q){
                    float hv = hS[(ng + 4*q)*SH + k];
                    aA[q] = fmaf(hv, wa, aA[q]);
                    aB[q] = fmaf(hv, wb, aB[q]);
                }
            }
            #pragma unroll
            for (int q = 0; q < 5; ++q){
                hA[(ng + 4*q)*SH + d] = aA[q];
                hB[(ng + 4*q)*SH + d] = aB[q];
            }
        }
        __syncthreads();

        const float4* W2g = reinterpret_cast<const float4*>(ew2 + l*4096);
        const float4* C1g = reinterpret_cast<const float4*>(cw1 + l*4096);

        // ---- edge tiles ----
        for (int tile = 0; tile < NTILE; ++tile){
            const int e0 = tile * 64;

            // t1 = silu(hA[r] + hB[c] + radial*w1c + b1) -> A1 k-major
            {
                int le = t & 63, kg = t >> 6;
                int e = e0 + le;
                bool v = (e < NEDGE);
                int r = 0, c = 0; float radial = 0.f;
                if (v){
                    r = e / 19; int jj = e - r*19; c = jj + (jj >= r);
                    float dx = x0[r] - x0[c], dy = x1[r] - x1[c];
                    radial = dx*dx + dy*dy;
                    if (kg == 0){
                        float inv = 1.f / (sqrtf(radial) + 1e-8f);
                        cdx[le] = dx * inv; cdy[le] = dy * inv;
                    }
                }
                #pragma unroll
                for (int kk = 0; kk < 16; ++kk){
                    int k = kg*16 + kk;
                    float o = 0.f;
                    if (v){
                        float pre = hA[r*SH + k] + hB[c*SH + k] + radial*w1c[k] + b1v[k];
                        o = silu_f(pre);
                    }
                    A1[k*64 + le] = o;   // conflict-free: le consecutive
                }
            }
            __syncthreads();

            // GEMM1: m = silu(A1 @ W2 + b2); gate with sigmoid(att) in-register; write Mm
            {
                int tx = t & 15, ty = t >> 4;
                float acc[4][4];
                #pragma unroll
                for (int i = 0; i < 4; ++i)
                    #pragma unroll
                    for (int j = 0; j < 4; ++j) acc[i][j] = 0.f;
                const float4* Ap = reinterpret_cast<const float4*>(A1) + ty;  // A1[k][4ty..]
                const float4* Bp = W2g + tx;
                #pragma unroll 8
                for (int k = 0; k < 64; ++k){
                    float4 a = Ap[k*16];          // broadcast LDS.128: 4 edges
                    float4 b = __ldg(Bp + k*16);  // LDG.128: 4 outputs (L1-hot)
                    acc[0][0]=fmaf(a.x,b.x,acc[0][0]); acc[0][1]=fmaf(a.x,b.y,acc[0][1]);
                    acc[0][2]=fmaf(a.x,b.z,acc[0][2]); acc[0][3]=fmaf(a.x,b.w,acc[0][3]);
                    acc[1][0]=fmaf(a.y,b.x,acc[1][0]); acc[1][1]=fmaf(a.y,b.y,acc[1][1]);
                    acc[1][2]=fmaf(a.y,b.z,acc[1][2]); acc[1][3]=fmaf(a.y,b.w,acc[1][3]);
                    acc[2][0]=fmaf(a.z,b.x,acc[2][0]); acc[2][1]=fmaf(a.z,b.y,acc[2][1]);
                    acc[2][2]=fmaf(a.z,b.z,acc[2][2]); acc[2][3]=fmaf(a.z,b.w,acc[2][3]);
                    acc[3][0]=fmaf(a.w,b.x,acc[3][0]); acc[3][1]=fmaf(a.w,b.y,acc[3][1]);
                    acc[3][2]=fmaf(a.w,b.z,acc[3][2]); acc[3][3]=fmaf(a.w,b.w,acc[3][3]);
                }
                float attp[4];
                #pragma unroll
                for (int i = 0; i < 4; ++i){
                    float s = 0.f;
                    #pragma unroll
                    for (int j = 0; j < 4; ++j){
                        float z = silu_f(acc[i][j] + b2v[4*tx + j]);
                        acc[i][j] = z;
                        s = fmaf(z, avv[4*tx + j], s);
                    }
                    attp[i] = s;
                }
                #pragma unroll
                for (int m = 8; m >= 1; m >>= 1){
                    #pragma unroll
                    for (int i = 0; i < 4; ++i)
                        attp[i] += __shfl_xor_sync(0xffffffffu, attp[i], m, 16);
                }
                float ab = abv[0];
                #pragma unroll
                for (int i = 0; i < 4; ++i){
                    float sg = sigm_f(attp[i] + ab);
                    float4 mv = make_float4(acc[i][0]*sg, acc[i][1]*sg,
                                            acc[i][2]*sg, acc[i][3]*sg);
                    *(float4*)(Mm + (4*ty + i)*SMM + 4*tx) = mv;  // conflict-free row write
                }
            }
            __syncthreads();

            // m_agg segment sum (reads gated Mm rows)
            {
                int o = t & 63, lg = t >> 6;
                float acc = 0.f; int curr = -1;
                for (int le = lg*16; le < lg*16 + 16; ++le){
                    int e = e0 + le;
                    if (e < NEDGE){
                        int r = e / 19;
                        if (r != curr){
                            if (curr >= 0) atomicAdd(mag + curr*SH + o, acc);
                            curr = r; acc = 0.f;
                        }
                        acc += Mm[le*SMM + o];
                    }
                }
                if (curr >= 0) atomicAdd(mag + curr*SH + o, acc);
            }

            // GEMM2: t3 = silu(Mm @ cw1 + cb1); w = tanh(t3 @ cw2); scatter coords
            {
                int tx = t & 15, ty = t >> 4;
                float acc[4][4];
                #pragma unroll
                for (int i = 0; i < 4; ++i)
                    #pragma unroll
                    for (int j = 0; j < 4; ++j) acc[i][j] = 0.f;
                const float4* Bp = C1g + tx;
                #pragma unroll 2
                for (int k0 = 0; k0 < 64; k0 += 4){
                    float4 a0 = *(const float4*)(Mm + (4*ty+0)*SMM + k0);  // broadcast
                    float4 a1 = *(const float4*)(Mm + (4*ty+1)*SMM + k0);
                    float4 a2 = *(const float4*)(Mm + (4*ty+2)*SMM + k0);
                    float4 a3 = *(const float4*)(Mm + (4*ty+3)*SMM + k0);
                    #pragma unroll
                    for (int kk = 0; kk < 4; ++kk){
                        float4 b = __ldg(Bp + (k0 + kk)*16);
                        float v0 = ((float*)&a0)[kk];
                        float v1 = ((float*)&a1)[kk];
                        float v2 = ((float*)&a2)[kk];
                        float v3 = ((float*)&a3)[kk];
                        acc[0][0]=fmaf(v0,b.x,acc[0][0]); acc[0][1]=fmaf(v0,b.y,acc[0][1]);
                        acc[0][2]=fmaf(v0,b.z,acc[0][2]); acc[0][3]=fmaf(v0,b.w,acc[0][3]);
                        acc[1][0]=fmaf(v1,b.x,acc[1][0]); acc[1][1]=fmaf(v1,b.y,acc[1][1]);
                        acc[1][2]=fmaf(v1,b.z,acc[1][2]); acc[1][3]=fmaf(v1,b.w,acc[1][3]);
                        acc[2][0]=fmaf(v2,b.x,acc[2][0]); acc[2][1]=fmaf(v2,b.y,acc[2][1]);
                        acc[2][2]=fmaf(v2,b.z,acc[2][2]); acc[2][3]=fmaf(v2,b.w,acc[2][3]);
                        acc[3][0]=fmaf(v3,b.x,acc[3][0]); acc[3][1]=fmaf(v3,b.y,acc[3][1]);
                        acc[3][2]=fmaf(v3,b.z,acc[3][2]); acc[3][3]=fmaf(v3,b.w,acc[3][3]);
                    }
                }
                float wp[4];
                #pragma unroll
                for (int i = 0; i < 4; ++i){
                    float s = 0.f;
                    #pragma unroll
                    for (int j = 0; j < 4; ++j){
                        float z = silu_f(acc[i][j] + cb1v[4*tx + j]);
                        s = fmaf(z, c2v[4*tx + j], s);
                    }
                    wp[i] = s;
                }
                #pragma unroll
                for (int m = 8; m >= 1; m >>= 1){
                    #pragma unroll
                    for (int i = 0; i < 4; ++i)
                        wp[i] += __shfl_xor_sync(0xffffffffu, wp[i], m, 16);
                }
                if (tx == 0){
                    #pragma unroll
                    for (int i = 0; i < 4; ++i){
                        int le = 4*ty + i, e = e0 + le;
                        if (e < NEDGE){
                            float w = tanhf(wp[i]);
                            int r = e / 19;
                            atomicAdd(aggx + r, cdx[le] * w);
                            atomicAdd(aggy + r, cdy[le] * w);
                        }
                    }
                }
            }
            __syncthreads();   // protects cdx/cdy + Mm before next tile overwrites
        } // tiles

        // ---- x update (cnt == 19 exactly) ----
        if (t < NNODE){
            x0[t] += aggx[t] * (1.f/19.f);
            x1[t] += aggy[t] * (1.f/19.f);
        }

        // ---- node MLP: h += silu([h,m_agg]@nw1+nb1) @ nw2 + nb2 ----
        float* z1 = A1;  // reuse (stride SH, 20*65 <= 4096)
        {
            int o = t & 63, ng = t >> 6;
            float acc[5];
            float bb = __ldg(nb1 + l*64 + o);
            #pragma unroll
            for (int q = 0; q < 5; ++q) acc[q] = bb;
            const float* w1 = nw1 + l*128*64;
            for (int k = 0; k < 64; ++k){
                float w = __ldg(w1 + k*64 + o);
                #pragma unroll
                for (int q = 0; q < 5; ++q) acc[q] = fmaf(hS[(ng+4*q)*SH + k], w, acc[q]);
            }
            for (int k = 0; k < 64; ++k){
                float w = __ldg(w1 + (64 + k)*64 + o);
                #pragma unroll
                for (int q = 0; q < 5; ++q) acc[q] = fmaf(mag[(ng+4*q)*SH + k], w, acc[q]);
            }
            #pragma unroll
            for (int q = 0; q < 5; ++q) z1[(ng+4*q)*SH + o] = silu_f(acc[q]);
        }
        __syncthreads();
        {
            int o = t & 63, ng = t >> 6;
            float acc[5];
            float bb = __ldg(nb2 + l*64 + o);
            #pragma unroll
            for (int q = 0; q < 5; ++q) acc[q] = bb;
            const float* w2 = nw2 + l*4096;
            for (int k = 0; k < 64; ++k){
                float w = __ldg(w2 + k*64 + o);
                #pragma unroll
                for (int q = 0; q < 5; ++q) acc[q] = fmaf(z1[(ng+4*q)*SH + k], w, acc[q]);
            }
            #pragma unroll
            for (int q = 0; q < 5; ++q) hS[(ng+4*q)*SH + o] += acc[q];
        }
        __syncthreads();
    } // layers

    // ---- value head ----
    float* z1 = A1;
    {
        int o = t & 63, ng = t >> 6;
        float acc[5];
        #pragma unroll
        for (int q = 0; q < 5; ++q){
            int n = ng + 4*q;
            float xsq = x0[n]*x0[n] + x1[n]*x1[n];
            acc[q] = fmaf(xsq, __ldg(fc1w + o), fc1b[o]);
        }
        for (int k = 0; k < 64; ++k){
            float w = __ldg(fc1w + (1 + k)*64 + o);
            #pragma unroll
            for (int q = 0; q < 5; ++q) acc[q] = fmaf(hS[(ng+4*q)*SH + k], w, acc[q]);
        }
        #pragma unroll
        for (int q = 0; q < 5; ++q) z1[(ng+4*q)*SH + o] = tanhf(acc[q]);
    }
    __syncthreads();
    if (t < 32){
        float v = 0.f;
        if (t < NNODE){
            v = __ldg(fc2b);
            for (int o = 0; o < 64; ++o) v = fmaf(z1[t*SH + o], __ldg(fc2w + o), v);
        }
        #pragma unroll
        for (int m = 16; m >= 1; m >>= 1) v += __shfl_xor_sync(0xffffffffu, v, m);
        if (t == 0) out[g] = v * (1.f / NNODE);
    }
    // rnn_states passthrough
    if (copy_rnn && t < 64) out[NB + g*64 + t] = rnn[g*64 + t];
}

extern "C" void kernel_launch(void* const* d_in, const int* in_sizes, int n_in,
                              void* d_out, int out_size)
{
    const float* obs   = (const float*)d_in[0];
    const float* rnn   = (const float*)d_in[1];
    // d_in[2] = masks (unused)
    const float* emb_w = (const float*)d_in[3];
    const float* emb_b = (const float*)d_in[4];
    const float* ew1   = (const float*)d_in[5];
    const float* eb1   = (const float*)d_in[6];
    const float* ew2   = (const float*)d_in[7];
    const float* eb2   = (const float*)d_in[8];
    const float* attw  = (const float*)d_in[9];
    const float* attb  = (const float*)d_in[10];
    const float* nw1   = (const float*)d_in[11];
    const float* nb1   = (const float*)d_in[12];
    const float* nw2   = (const float*)d_in[13];
    const float* nb2   = (const float*)d_in[14];
    const float* cw1   = (const float*)d_in[15];
    const float* cb1   = (const float*)d_in[16];
    const float* cw2   = (const float*)d_in[17];
    const float* fc1w  = (const float*)d_in[18];
    const float* fc1b  = (const float*)d_in[19];
    const float* fc2w  = (const float*)d_in[20];
    const float* fc2b  = (const float*)d_in[21];
    // d_in[22], d_in[23] = edge_row/edge_col (recomputed analytically)

    const size_t smem_bytes = (size_t)SMEM_FLOATS * sizeof(float);
    cudaFuncSetAttribute(egnn_critic_kernel,
                         cudaFuncAttributeMaxDynamicSharedMemorySize,
                         (int)smem_bytes);

    int copy_rnn = (out_size >= NB + NB*HID) ? 1 : 0;

    egnn_critic_kernel<<<NB, BLK, smem_bytes>>>(
        obs, rnn, emb_w, emb_b, ew1, eb1, ew2, eb2, attw, attb,
        nw1, nb1, nw2, nb2, cw1, cb1, cw2, fc1w, fc1b, fc2w, fc2b,
        (float*)d_out, copy_rnn);
}